// round 11
// baseline (speedup 1.0000x reference)
#include <cuda_runtime.h>
#include <cuda_bf16.h>
#include <cstdint>

#define B_ 8
#define S_ 256
#define H_ 768
#define K_ 256
#define P_ 50
#define VSTRIDE 132    // V smem row stride in b32: bank = 4*group+c -> conflict-free
#define FOLD 2.8853900817779268f   // 2*log2(e): pre-scales tanh arg for ex2

// Scratch for the two projection GEMMs (allocation-free rule: device globals)
// NOTE: both are PRE-SCALED by FOLD (only consumed by the fused kernel's ex2).
__device__ __align__(16) float g_left [B_ * S_ * K_];   // (x@u_a + b_s) * FOLD
__device__ __align__(16) float g_right[B_ * S_ * K_];   // (x@w_a) * FOLD

// ---------------- packed f32x2 helpers (Blackwell FFMA2 path) ----------------
__device__ __forceinline__ unsigned long long pack2(float a, float b) {
    unsigned long long r;
    asm("mov.b64 %0, {%1, %2};" : "=l"(r)
        : "r"(__float_as_uint(a)), "r"(__float_as_uint(b)));
    return r;
}
__device__ __forceinline__ void fma2(unsigned long long& d,
                                     unsigned long long a, unsigned long long b) {
    asm("fma.rn.f32x2 %0, %1, %2, %0;" : "+l"(d) : "l"(a), "l"(b));
}
__device__ __forceinline__ void unpack2(unsigned long long p, float& lo, float& hi) {
    unsigned int l, h;
    asm("mov.b64 {%0, %1}, %2;" : "=r"(l), "=r"(h) : "l"(p));
    lo = __uint_as_float(l);
    hi = __uint_as_float(h);
}

// ---------------- bf16 split helpers ----------------
// pack two f32 -> bf16x2; first arg lands in the LOW 16 bits
__device__ __forceinline__ uint32_t bf16x2(float lo, float hi) {
    uint32_t r;
    asm("cvt.rn.bf16x2.f32 %0, %1, %2;" : "=r"(r) : "f"(hi), "f"(lo));
    return r;
}
__device__ __forceinline__ float lo16f(uint32_t p) { return __uint_as_float(p << 16); }
__device__ __forceinline__ float hi16f(uint32_t p) { return __uint_as_float(p & 0xffff0000u); }

// tanh with argument PRE-SCALED by 2*log2(e): t = 1 - 2/(2^a' + 1)
__device__ __forceinline__ float tanh_pre(float a) {
    float e;  asm("ex2.approx.f32 %0, %1;" : "=f"(e) : "f"(a));
    float den = e + 1.0f;
    float r;  asm("rcp.approx.f32 %0, %1;" : "=f"(r) : "f"(den));
    return fmaf(-2.0f, r, 1.0f);
}

// classic warp-level bf16 MMA (sm_80+; works on sm_100 base target)
__device__ __forceinline__ void mma16816(float* d, uint32_t a0, uint32_t a1,
                                         uint32_t a2, uint32_t a3,
                                         uint32_t b0, uint32_t b1) {
    asm volatile(
        "mma.sync.aligned.m16n8k16.row.col.f32.bf16.bf16.f32 "
        "{%0,%1,%2,%3}, {%4,%5,%6,%7}, {%8,%9}, {%0,%1,%2,%3};"
        : "+f"(d[0]), "+f"(d[1]), "+f"(d[2]), "+f"(d[3])
        : "r"(a0), "r"(a1), "r"(a2), "r"(a3), "r"(b0), "r"(b1));
}

// ---------------- Kernel 1: left/right projections (fused bias + FOLD scale) --------
__global__ __launch_bounds__(256) void gemm_lr_kernel(
    const float* __restrict__ x, const float* __restrict__ u_a,
    const float* __restrict__ w_a, const float* __restrict__ b_s)
{
    __shared__ float sX[16][64];
    __shared__ float sW[16][64];

    const int z = blockIdx.z;
    const float* __restrict__ w = z ? w_a : u_a;
    float* __restrict__ outp = z ? g_right : g_left;

    const int row0 = blockIdx.y * 64;
    const int col0 = blockIdx.x * 64;
    const int tid = threadIdx.x;
    const int tx = tid & 15, ty = tid >> 4;

    unsigned long long acc[4][2];
#pragma unroll
    for (int i = 0; i < 4; i++) { acc[i][0] = 0ull; acc[i][1] = 0ull; }

    const int lr = tid >> 2;
    const int lk = (tid & 3) << 2;
    const int wk = tid >> 4;
    const int wc = (tid & 15) << 2;

    for (int k0 = 0; k0 < H_; k0 += 16) {
        float4 gx = *(const float4*)&x[(row0 + lr) * H_ + k0 + lk];
        float4 gw = *(const float4*)&w[(k0 + wk) * K_ + col0 + wc];
        __syncthreads();
        sX[lk + 0][lr] = gx.x; sX[lk + 1][lr] = gx.y;
        sX[lk + 2][lr] = gx.z; sX[lk + 3][lr] = gx.w;
        *(float4*)&sW[wk][wc] = gw;
        __syncthreads();
#pragma unroll
        for (int kk = 0; kk < 16; kk++) {
            float4 a4 = *(const float4*)&sX[kk][ty * 4];
            float4 b4 = *(const float4*)&sW[kk][tx * 4];
            unsigned long long b01 = pack2(b4.x, b4.y);
            unsigned long long b23 = pack2(b4.z, b4.w);
            unsigned long long a0 = pack2(a4.x, a4.x);
            unsigned long long a1 = pack2(a4.y, a4.y);
            unsigned long long a2 = pack2(a4.z, a4.z);
            unsigned long long a3 = pack2(a4.w, a4.w);
            fma2(acc[0][0], a0, b01); fma2(acc[0][1], a0, b23);
            fma2(acc[1][0], a1, b01); fma2(acc[1][1], a1, b23);
            fma2(acc[2][0], a2, b01); fma2(acc[2][1], a2, b23);
            fma2(acc[3][0], a3, b01); fma2(acc[3][1], a3, b23);
        }
    }

    const int col = col0 + tx * 4;
#pragma unroll
    for (int i = 0; i < 4; i++) {
        float4 o;
        unpack2(acc[i][0], o.x, o.y);
        unpack2(acc[i][1], o.z, o.w);
        if (!z) {
            o.x = (o.x + b_s[col + 0]) * FOLD;
            o.y = (o.y + b_s[col + 1]) * FOLD;
            o.z = (o.z + b_s[col + 2]) * FOLD;
            o.w = (o.w + b_s[col + 3]) * FOLD;
        } else {
            o.x *= FOLD; o.y *= FOLD; o.z *= FOLD; o.w *= FOLD;
        }
        *(float4*)&outp[(row0 + ty * 4 + i) * K_ + col] = o;
    }
}

// ---------------- Kernel 2: register-direct tanh -> mma.sync bf16-split, m32/warp ----
// CTA = 512 threads = 16 warps, covers TWO i-rows x 256 j.
// Warp w: i = i0 + (w>>3); j-range = (w&7)*32 .. +32 (two m16 A-fragment sets).
// Pass-major MMA ordering: consecutive HMMAs hit 14 independent accumulators
// (R10's nt-major had 3 dependent HMMAs back-to-back on each acc).
#define SVHI_OFF 2048
#define SVLO_OFF (SVHI_OFF + 56 * VSTRIDE * 4)
#define SMEM2_BYTES (SVHI_OFF + 2 * 56 * VSTRIDE * 4)   // 61184

__global__ __launch_bounds__(512) void fused_tanh_mma_kernel(
    const float* __restrict__ v, float* __restrict__ out)
{
    extern __shared__ char smem[];
    float*    sL   = (float*)smem;                  // 2 rows x 256 f32 (pre-scaled)
    uint32_t* sVhi = (uint32_t*)(smem + SVHI_OFF);  // [56][VSTRIDE] b32 (k-pairs)
    uint32_t* sVlo = (uint32_t*)(smem + SVLO_OFF);

    const int tid = threadIdx.x;
    const int i0 = blockIdx.x * 2;
    const int b  = blockIdx.y;

    // stage two l rows
    sL[tid] = g_left[(size_t)(b * S_ + i0 + (tid >> 8)) * K_ + (tid & 255)];

    // stage V^T hi/lo: row n (0..55, zero-padded >=50), col kk packs (k=2kk, 2kk+1)
    for (int idx = tid; idx < 56 * 128; idx += 512) {
        int n = idx >> 7;
        int kk = idx & 127;
        int k = kk << 1;
        float v0 = 0.0f, v1 = 0.0f;
        if (n < P_) { v0 = v[k * P_ + n]; v1 = v[(k + 1) * P_ + n]; }
        uint32_t hp = bf16x2(v0, v1);
        uint32_t lp = bf16x2(v0 - lo16f(hp), v1 - hi16f(hp));
        sVhi[n * VSTRIDE + kk] = hp;
        sVlo[n * VSTRIDE + kk] = lp;
    }
    __syncthreads();

    const int w = tid >> 5, lane = tid & 31;
    const int group = lane >> 2, c = lane & 3;
    const int iw = w >> 3;                  // which of the 2 i-rows
    const int jb = (w & 7) * 32;            // warp's j base (32 rows)
    const float* lrow = sL + iw * 256;

    // 4 A rows per thread: j = jb+group, +8, +16, +24 (one base ptr + imm offsets)
    const float* rbase = g_right + (size_t)(b * S_ + jb + group) * K_ + 2 * c;

    float d0[7][4], d1[7][4];
#pragma unroll
    for (int nt = 0; nt < 7; nt++)
#pragma unroll
        for (int q = 0; q < 4; q++) { d0[nt][q] = 0.0f; d1[nt][q] = 0.0f; }

    // prefetch chunk 0 r-values (L2-resident; coalesced)
    float2 rlo[4], rhi[4];
#pragma unroll
    for (int s = 0; s < 4; s++) {
        rlo[s] = *(const float2*)(rbase + s * 8 * K_);
        rhi[s] = *(const float2*)(rbase + s * 8 * K_ + 8);
    }

#pragma unroll 4
    for (int ch = 0; ch < 16; ch++) {
        const int k0 = ch * 16;
        float2 l0 = *(const float2*)&lrow[k0 + 2 * c];
        float2 l2 = *(const float2*)&lrow[k0 + 2 * c + 8];

        // 16 tanh (pre-scaled args: 1 add + ex2 + add + rcp + fma each)
        float tl[4][2], th[4][2];
#pragma unroll
        for (int s = 0; s < 4; s++) {
            tl[s][0] = tanh_pre(l0.x + rlo[s].x);
            tl[s][1] = tanh_pre(l0.y + rlo[s].y);
            th[s][0] = tanh_pre(l2.x + rhi[s].x);
            th[s][1] = tanh_pre(l2.y + rhi[s].y);
        }

        // prefetch next chunk's r while tanh/mma proceed
        if (ch < 15) {
#pragma unroll
            for (int s = 0; s < 4; s++) {
                rlo[s] = *(const float2*)(rbase + s * 8 * K_ + (ch + 1) * 16);
                rhi[s] = *(const float2*)(rbase + s * 8 * K_ + (ch + 1) * 16 + 8);
            }
        }

        // pack A fragments: set0 = rows (group, group+8), set1 = (group+16, +24)
        uint32_t aH[8], aL[8];
#pragma unroll
        for (int s = 0; s < 2; s++) {
            int ra = 2 * s, rb = 2 * s + 1;
            aH[4*s+0] = bf16x2(tl[ra][0], tl[ra][1]);
            aH[4*s+1] = bf16x2(tl[rb][0], tl[rb][1]);
            aH[4*s+2] = bf16x2(th[ra][0], th[ra][1]);
            aH[4*s+3] = bf16x2(th[rb][0], th[rb][1]);
            aL[4*s+0] = bf16x2(tl[ra][0] - lo16f(aH[4*s+0]), tl[ra][1] - hi16f(aH[4*s+0]));
            aL[4*s+1] = bf16x2(tl[rb][0] - lo16f(aH[4*s+1]), tl[rb][1] - hi16f(aH[4*s+1]));
            aL[4*s+2] = bf16x2(th[ra][0] - lo16f(aH[4*s+2]), th[ra][1] - hi16f(aH[4*s+2]));
            aL[4*s+3] = bf16x2(th[rb][0] - lo16f(aH[4*s+3]), th[rb][1] - hi16f(aH[4*s+3]));
        }

        const uint32_t* ph = sVhi + (ch << 3) + c;   // + n*VSTRIDE
        const uint32_t* pl = sVlo + (ch << 3) + c;

        // pass 1: hi*hi — load and RETAIN Bh fragments
        uint32_t bh0[7], bh1[7];
#pragma unroll
        for (int nt = 0; nt < 7; nt++) {
            const int off = (nt * 8 + group) * VSTRIDE;
            bh0[nt] = ph[off]; bh1[nt] = ph[off + 4];
            mma16816(d0[nt], aH[0], aH[1], aH[2], aH[3], bh0[nt], bh1[nt]);
            mma16816(d1[nt], aH[4], aH[5], aH[6], aH[7], bh0[nt], bh1[nt]);
        }
        // pass 2: lo*hi — reuse Bh regs
#pragma unroll
        for (int nt = 0; nt < 7; nt++) {
            mma16816(d0[nt], aL[0], aL[1], aL[2], aL[3], bh0[nt], bh1[nt]);
            mma16816(d1[nt], aL[4], aL[5], aL[6], aL[7], bh0[nt], bh1[nt]);
        }
        // pass 3: hi*lo — stream Bl
#pragma unroll
        for (int nt = 0; nt < 7; nt++) {
            const int off = (nt * 8 + group) * VSTRIDE;
            uint32_t b0l = pl[off], b1l = pl[off + 4];
            mma16816(d0[nt], aH[0], aH[1], aH[2], aH[3], b0l, b1l);
            mma16816(d1[nt], aH[4], aH[5], aH[6], aH[7], b0l, b1l);
        }
    }

    // epilogue: rows jb+group (+8, +16, +24), cols p = nt*8 + 2c (+1); only p<50
    float* obase = out + (size_t)(b * S_ + i0 + iw) * S_ * P_ + (size_t)(jb + group) * P_;
#pragma unroll
    for (int nt = 0; nt < 7; nt++) {
        const int p0 = nt * 8 + 2 * c;
        if (p0 < P_) {   // p0 even, p0<=48 -> p0+1<=49 safe
            *(float2*)(obase + 0 * 8 * P_ + p0) = make_float2(d0[nt][0], d0[nt][1]);
            *(float2*)(obase + 1 * 8 * P_ + p0) = make_float2(d0[nt][2], d0[nt][3]);
            *(float2*)(obase + 2 * 8 * P_ + p0) = make_float2(d1[nt][0], d1[nt][1]);
            *(float2*)(obase + 3 * 8 * P_ + p0) = make_float2(d1[nt][2], d1[nt][3]);
        }
    }
}

extern "C" void kernel_launch(void* const* d_in, const int* in_sizes, int n_in,
                              void* d_out, int out_size) {
    const float* x   = (const float*)d_in[0];
    const float* u_a = (const float*)d_in[1];
    const float* w_a = (const float*)d_in[2];
    const float* b_s = (const float*)d_in[3];
    const float* v   = (const float*)d_in[4];
    float* out = (float*)d_out;

    cudaFuncSetAttribute(fused_tanh_mma_kernel,
                         cudaFuncAttributeMaxDynamicSharedMemorySize, SMEM2_BYTES);

    dim3 g1(K_ / 64, (B_ * S_) / 64, 2);      // (4, 32, 2)
    gemm_lr_kernel<<<g1, 256>>>(x, u_a, w_a, b_s);

    dim3 g2(S_ / 2, B_);                       // 1024 CTAs (2 i-rows each)
    fused_tanh_mma_kernel<<<g2, 512, SMEM2_BYTES>>>(v, out);
}

// round 12
// speedup vs baseline: 1.0319x; 1.0319x over previous
#include <cuda_runtime.h>
#include <cuda_bf16.h>
#include <cstdint>

#define B_ 8
#define S_ 256
#define H_ 768
#define K_ 256
#define P_ 50
#define VSTRIDE 132    // V smem row stride in b32: bank = 4*group+c -> conflict-free
#define FOLD 2.8853900817779268f   // 2*log2(e): pre-scales tanh arg for ex2

// Scratch for the two projection GEMMs (allocation-free rule: device globals)
// NOTE: both are PRE-SCALED by FOLD (only consumed by the fused kernel's ex2).
__device__ __align__(16) float g_left [B_ * S_ * K_];   // (x@u_a + b_s) * FOLD
__device__ __align__(16) float g_right[B_ * S_ * K_];   // (x@w_a) * FOLD

// ---------------- packed f32x2 helpers (Blackwell FFMA2 path) ----------------
__device__ __forceinline__ unsigned long long pack2(float a, float b) {
    unsigned long long r;
    asm("mov.b64 %0, {%1, %2};" : "=l"(r)
        : "r"(__float_as_uint(a)), "r"(__float_as_uint(b)));
    return r;
}
__device__ __forceinline__ void fma2(unsigned long long& d,
                                     unsigned long long a, unsigned long long b) {
    asm("fma.rn.f32x2 %0, %1, %2, %0;" : "+l"(d) : "l"(a), "l"(b));
}
__device__ __forceinline__ void unpack2(unsigned long long p, float& lo, float& hi) {
    unsigned int l, h;
    asm("mov.b64 {%0, %1}, %2;" : "=r"(l), "=r"(h) : "l"(p));
    lo = __uint_as_float(l);
    hi = __uint_as_float(h);
}

// ---------------- bf16 split helpers ----------------
// pack two f32 -> bf16x2; first arg lands in the LOW 16 bits
__device__ __forceinline__ uint32_t bf16x2(float lo, float hi) {
    uint32_t r;
    asm("cvt.rn.bf16x2.f32 %0, %1, %2;" : "=r"(r) : "f"(hi), "f"(lo));
    return r;
}
__device__ __forceinline__ float lo16f(uint32_t p) { return __uint_as_float(p << 16); }
__device__ __forceinline__ float hi16f(uint32_t p) { return __uint_as_float(p & 0xffff0000u); }

// tanh with argument PRE-SCALED by 2*log2(e): t = 1 - 2/(2^a' + 1)
__device__ __forceinline__ float tanh_pre(float a) {
    float e;  asm("ex2.approx.f32 %0, %1;" : "=f"(e) : "f"(a));
    float den = e + 1.0f;
    float r;  asm("rcp.approx.f32 %0, %1;" : "=f"(r) : "f"(den));
    return fmaf(-2.0f, r, 1.0f);
}

// classic warp-level bf16 MMA (sm_80+; works on sm_100 base target)
__device__ __forceinline__ void mma16816(float* d, uint32_t a0, uint32_t a1,
                                         uint32_t a2, uint32_t a3,
                                         uint32_t b0, uint32_t b1) {
    asm volatile(
        "mma.sync.aligned.m16n8k16.row.col.f32.bf16.bf16.f32 "
        "{%0,%1,%2,%3}, {%4,%5,%6,%7}, {%8,%9}, {%0,%1,%2,%3};"
        : "+f"(d[0]), "+f"(d[1]), "+f"(d[2]), "+f"(d[3])
        : "r"(a0), "r"(a1), "r"(a2), "r"(a3), "r"(b0), "r"(b1));
}

// ---------------- Kernel 1: left/right projections (fused bias + FOLD scale) --------
__global__ __launch_bounds__(256) void gemm_lr_kernel(
    const float* __restrict__ x, const float* __restrict__ u_a,
    const float* __restrict__ w_a, const float* __restrict__ b_s)
{
    __shared__ float sX[16][64];
    __shared__ float sW[16][64];

    const int z = blockIdx.z;
    const float* __restrict__ w = z ? w_a : u_a;
    float* __restrict__ outp = z ? g_right : g_left;

    const int row0 = blockIdx.y * 64;
    const int col0 = blockIdx.x * 64;
    const int tid = threadIdx.x;
    const int tx = tid & 15, ty = tid >> 4;

    unsigned long long acc[4][2];
#pragma unroll
    for (int i = 0; i < 4; i++) { acc[i][0] = 0ull; acc[i][1] = 0ull; }

    const int lr = tid >> 2;
    const int lk = (tid & 3) << 2;
    const int wk = tid >> 4;
    const int wc = (tid & 15) << 2;

    for (int k0 = 0; k0 < H_; k0 += 16) {
        float4 gx = *(const float4*)&x[(row0 + lr) * H_ + k0 + lk];
        float4 gw = *(const float4*)&w[(k0 + wk) * K_ + col0 + wc];
        __syncthreads();
        sX[lk + 0][lr] = gx.x; sX[lk + 1][lr] = gx.y;
        sX[lk + 2][lr] = gx.z; sX[lk + 3][lr] = gx.w;
        *(float4*)&sW[wk][wc] = gw;
        __syncthreads();
#pragma unroll
        for (int kk = 0; kk < 16; kk++) {
            float4 a4 = *(const float4*)&sX[kk][ty * 4];
            float4 b4 = *(const float4*)&sW[kk][tx * 4];
            unsigned long long b01 = pack2(b4.x, b4.y);
            unsigned long long b23 = pack2(b4.z, b4.w);
            unsigned long long a0 = pack2(a4.x, a4.x);
            unsigned long long a1 = pack2(a4.y, a4.y);
            unsigned long long a2 = pack2(a4.z, a4.z);
            unsigned long long a3 = pack2(a4.w, a4.w);
            fma2(acc[0][0], a0, b01); fma2(acc[0][1], a0, b23);
            fma2(acc[1][0], a1, b01); fma2(acc[1][1], a1, b23);
            fma2(acc[2][0], a2, b01); fma2(acc[2][1], a2, b23);
            fma2(acc[3][0], a3, b01); fma2(acc[3][1], a3, b23);
        }
    }

    const int col = col0 + tx * 4;
#pragma unroll
    for (int i = 0; i < 4; i++) {
        float4 o;
        unpack2(acc[i][0], o.x, o.y);
        unpack2(acc[i][1], o.z, o.w);
        if (!z) {
            o.x = (o.x + b_s[col + 0]) * FOLD;
            o.y = (o.y + b_s[col + 1]) * FOLD;
            o.z = (o.z + b_s[col + 2]) * FOLD;
            o.w = (o.w + b_s[col + 3]) * FOLD;
        } else {
            o.x *= FOLD; o.y *= FOLD; o.z *= FOLD; o.w *= FOLD;
        }
        *(float4*)&outp[(row0 + ty * 4 + i) * K_ + col] = o;
    }
}

// ---------------- Kernel 2: register-direct tanh -> mma.sync bf16-split, m32/warp ----
// CTA = 256 threads = 8 warps, ONE i-row x 256 j  -> 2 CTAs/SM (phase-decorrelated,
// so one CTA's MUFU/tanh phase overlaps the other's HMMA phase).
// Warp w: j-range = w*32 .. +32 (two m16 A-fragment sets).
// Pass-major MMA (14 independent accumulators between dependent HMMAs), B reloaded
// from smem per pass (no Bh register retention -> regs stay ~105).
#define SVHI_OFF 1024
#define SVLO_OFF (SVHI_OFF + 56 * VSTRIDE * 4)
#define SMEM2_BYTES (SVHI_OFF + 2 * 56 * VSTRIDE * 4)   // 60160

__global__ __launch_bounds__(256) void fused_tanh_mma_kernel(
    const float* __restrict__ v, float* __restrict__ out)
{
    extern __shared__ char smem[];
    float*    sL   = (float*)smem;                  // 256 f32 (pre-scaled l row)
    uint32_t* sVhi = (uint32_t*)(smem + SVHI_OFF);  // [56][VSTRIDE] b32 (k-pairs)
    uint32_t* sVlo = (uint32_t*)(smem + SVLO_OFF);

    const int tid = threadIdx.x;
    const int i = blockIdx.x;
    const int b = blockIdx.y;

    // stage l row
    sL[tid] = g_left[(size_t)(b * S_ + i) * K_ + tid];

    // stage V^T hi/lo: row n (0..55, zero-padded >=50), col kk packs (k=2kk, 2kk+1)
    for (int idx = tid; idx < 56 * 128; idx += 256) {
        int n = idx >> 7;
        int kk = idx & 127;
        int k = kk << 1;
        float v0 = 0.0f, v1 = 0.0f;
        if (n < P_) { v0 = v[k * P_ + n]; v1 = v[(k + 1) * P_ + n]; }
        uint32_t hp = bf16x2(v0, v1);
        uint32_t lp = bf16x2(v0 - lo16f(hp), v1 - hi16f(hp));
        sVhi[n * VSTRIDE + kk] = hp;
        sVlo[n * VSTRIDE + kk] = lp;
    }
    __syncthreads();

    const int w = tid >> 5, lane = tid & 31;
    const int group = lane >> 2, c = lane & 3;
    const int jb = w * 32;                  // warp's j base (32 rows)

    // 4 A rows per thread: j = jb+group, +8, +16, +24 (one base ptr + imm offsets)
    const float* rbase = g_right + (size_t)(b * S_ + jb + group) * K_ + 2 * c;

    float d0[7][4], d1[7][4];
#pragma unroll
    for (int nt = 0; nt < 7; nt++)
#pragma unroll
        for (int q = 0; q < 4; q++) { d0[nt][q] = 0.0f; d1[nt][q] = 0.0f; }

    // prefetch chunk 0 r-values (L2-resident; coalesced)
    float2 rlo[4], rhi[4];
#pragma unroll
    for (int s = 0; s < 4; s++) {
        rlo[s] = *(const float2*)(rbase + s * 8 * K_);
        rhi[s] = *(const float2*)(rbase + s * 8 * K_ + 8);
    }

#pragma unroll
    for (int ch = 0; ch < 16; ch++) {
        const int k0 = ch * 16;
        float2 l0 = *(const float2*)&sL[k0 + 2 * c];
        float2 l2 = *(const float2*)&sL[k0 + 2 * c + 8];

        // 16 tanh (pre-scaled args: add + ex2 + add + rcp + fma each)
        float tl[4][2], th[4][2];
#pragma unroll
        for (int s = 0; s < 4; s++) {
            tl[s][0] = tanh_pre(l0.x + rlo[s].x);
            tl[s][1] = tanh_pre(l0.y + rlo[s].y);
            th[s][0] = tanh_pre(l2.x + rhi[s].x);
            th[s][1] = tanh_pre(l2.y + rhi[s].y);
        }

        // prefetch next chunk's r while tanh/mma proceed
        if (ch < 15) {
#pragma unroll
            for (int s = 0; s < 4; s++) {
                rlo[s] = *(const float2*)(rbase + s * 8 * K_ + (ch + 1) * 16);
                rhi[s] = *(const float2*)(rbase + s * 8 * K_ + (ch + 1) * 16 + 8);
            }
        }

        // pack A fragments: set0 = rows (group, group+8), set1 = (group+16, +24)
        uint32_t aH[8], aL[8];
#pragma unroll
        for (int s = 0; s < 2; s++) {
            int ra = 2 * s, rb = 2 * s + 1;
            aH[4*s+0] = bf16x2(tl[ra][0], tl[ra][1]);
            aH[4*s+1] = bf16x2(tl[rb][0], tl[rb][1]);
            aH[4*s+2] = bf16x2(th[ra][0], th[ra][1]);
            aH[4*s+3] = bf16x2(th[rb][0], th[rb][1]);
            aL[4*s+0] = bf16x2(tl[ra][0] - lo16f(aH[4*s+0]), tl[ra][1] - hi16f(aH[4*s+0]));
            aL[4*s+1] = bf16x2(tl[rb][0] - lo16f(aH[4*s+1]), tl[rb][1] - hi16f(aH[4*s+1]));
            aL[4*s+2] = bf16x2(th[ra][0] - lo16f(aH[4*s+2]), th[ra][1] - hi16f(aH[4*s+2]));
            aL[4*s+3] = bf16x2(th[rb][0] - lo16f(aH[4*s+3]), th[rb][1] - hi16f(aH[4*s+3]));
        }

        const uint32_t* ph = sVhi + (ch << 3) + c;   // + n*VSTRIDE
        const uint32_t* pl = sVlo + (ch << 3) + c;

        // pass 1: hi*hi (14 independent HMMAs)
#pragma unroll
        for (int nt = 0; nt < 7; nt++) {
            const int off = (nt * 8 + group) * VSTRIDE;
            uint32_t b0 = ph[off], b1 = ph[off + 4];
            mma16816(d0[nt], aH[0], aH[1], aH[2], aH[3], b0, b1);
            mma16816(d1[nt], aH[4], aH[5], aH[6], aH[7], b0, b1);
        }
        // pass 2: lo*hi (B reloaded -- cheap LDS, keeps regs low)
#pragma unroll
        for (int nt = 0; nt < 7; nt++) {
            const int off = (nt * 8 + group) * VSTRIDE;
            uint32_t b0 = ph[off], b1 = ph[off + 4];
            mma16816(d0[nt], aL[0], aL[1], aL[2], aL[3], b0, b1);
            mma16816(d1[nt], aL[4], aL[5], aL[6], aL[7], b0, b1);
        }
        // pass 3: hi*lo
#pragma unroll
        for (int nt = 0; nt < 7; nt++) {
            const int off = (nt * 8 + group) * VSTRIDE;
            uint32_t b0 = pl[off], b1 = pl[off + 4];
            mma16816(d0[nt], aH[0], aH[1], aH[2], aH[3], b0, b1);
            mma16816(d1[nt], aH[4], aH[5], aH[6], aH[7], b0, b1);
        }
    }

    // epilogue: rows jb+group (+8, +16, +24), cols p = nt*8 + 2c (+1); only p<50
    float* obase = out + (size_t)(b * S_ + i) * S_ * P_ + (size_t)(jb + group) * P_;
#pragma unroll
    for (int nt = 0; nt < 7; nt++) {
        const int p0 = nt * 8 + 2 * c;
        if (p0 < P_) {   // p0 even, p0<=48 -> p0+1<=49 safe
            *(float2*)(obase + 0 * 8 * P_ + p0) = make_float2(d0[nt][0], d0[nt][1]);
            *(float2*)(obase + 1 * 8 * P_ + p0) = make_float2(d0[nt][2], d0[nt][3]);
            *(float2*)(obase + 2 * 8 * P_ + p0) = make_float2(d1[nt][0], d1[nt][1]);
            *(float2*)(obase + 3 * 8 * P_ + p0) = make_float2(d1[nt][2], d1[nt][3]);
        }
    }
}

extern "C" void kernel_launch(void* const* d_in, const int* in_sizes, int n_in,
                              void* d_out, int out_size) {
    const float* x   = (const float*)d_in[0];
    const float* u_a = (const float*)d_in[1];
    const float* w_a = (const float*)d_in[2];
    const float* b_s = (const float*)d_in[3];
    const float* v   = (const float*)d_in[4];
    float* out = (float*)d_out;

    cudaFuncSetAttribute(fused_tanh_mma_kernel,
                         cudaFuncAttributeMaxDynamicSharedMemorySize, SMEM2_BYTES);

    dim3 g1(K_ / 64, (B_ * S_) / 64, 2);      // (4, 32, 2)
    gemm_lr_kernel<<<g1, 256>>>(x, u_a, w_a, b_s);

    dim3 g2(S_, B_);                           // 2048 CTAs (1 i-row each, 2/SM)
    fused_tanh_mma_kernel<<<g2, 256, SMEM2_BYTES>>>(v, out);
}

// round 14
// speedup vs baseline: 1.0931x; 1.0593x over previous
#include <cuda_runtime.h>
#include <cuda_bf16.h>
#include <cstdint>

#define B_ 8
#define S_ 256
#define H_ 768
#define K_ 256
#define P_ 50
#define VSTRIDE 132    // V smem row stride in b32: bank = 4*group+c -> conflict-free

// Scratch for the two projection GEMMs (allocation-free rule: device globals)
__device__ __align__(16) float g_left [B_ * S_ * K_];   // left  = x@u_a + b_s
__device__ __align__(16) float g_right[B_ * S_ * K_];   // right = x@w_a

// ---------------- packed f32x2 helpers (Blackwell FFMA2 path) ----------------
__device__ __forceinline__ unsigned long long pack2(float a, float b) {
    unsigned long long r;
    asm("mov.b64 %0, {%1, %2};" : "=l"(r)
        : "r"(__float_as_uint(a)), "r"(__float_as_uint(b)));
    return r;
}
__device__ __forceinline__ void fma2(unsigned long long& d,
                                     unsigned long long a, unsigned long long b) {
    asm("fma.rn.f32x2 %0, %1, %2, %0;" : "+l"(d) : "l"(a), "l"(b));
}
__device__ __forceinline__ void unpack2(unsigned long long p, float& lo, float& hi) {
    unsigned int l, h;
    asm("mov.b64 {%0, %1}, %2;" : "=r"(l), "=r"(h) : "l"(p));
    lo = __uint_as_float(l);
    hi = __uint_as_float(h);
}

// ---------------- bf16 split helpers ----------------
// pack two f32 -> bf16x2; first arg lands in the LOW 16 bits
__device__ __forceinline__ uint32_t bf16x2(float lo, float hi) {
    uint32_t r;
    asm("cvt.rn.bf16x2.f32 %0, %1, %2;" : "=r"(r) : "f"(hi), "f"(lo));
    return r;
}
__device__ __forceinline__ float lo16f(uint32_t p) { return __uint_as_float(p << 16); }
__device__ __forceinline__ float hi16f(uint32_t p) { return __uint_as_float(p & 0xffff0000u); }

// HW tanh: single MUFU op (sm_75+, valid on base sm_100 target).
// Max abs err ~1e-4 -> adds ~1.5e-4 rel to output (budget 1e-3; bf16-split is 4e-6).
__device__ __forceinline__ float tanh_fast(float a) {
    float r;
    asm("tanh.approx.f32 %0, %1;" : "=f"(r) : "f"(a));
    return r;
}

// classic warp-level bf16 MMA (sm_80+; works on sm_100 base target)
__device__ __forceinline__ void mma16816(float* d, uint32_t a0, uint32_t a1,
                                         uint32_t a2, uint32_t a3,
                                         uint32_t b0, uint32_t b1) {
    asm volatile(
        "mma.sync.aligned.m16n8k16.row.col.f32.bf16.bf16.f32 "
        "{%0,%1,%2,%3}, {%4,%5,%6,%7}, {%8,%9}, {%0,%1,%2,%3};"
        : "+f"(d[0]), "+f"(d[1]), "+f"(d[2]), "+f"(d[3])
        : "r"(a0), "r"(a1), "r"(a2), "r"(a3), "r"(b0), "r"(b1));
}

// ---------------- Kernel 1: left/right projections (fused bias) ----------------
__global__ __launch_bounds__(256) void gemm_lr_kernel(
    const float* __restrict__ x, const float* __restrict__ u_a,
    const float* __restrict__ w_a, const float* __restrict__ b_s)
{
    __shared__ float sX[16][64];
    __shared__ float sW[16][64];

    const int z = blockIdx.z;
    const float* __restrict__ w = z ? w_a : u_a;
    float* __restrict__ outp = z ? g_right : g_left;

    const int row0 = blockIdx.y * 64;
    const int col0 = blockIdx.x * 64;
    const int tid = threadIdx.x;
    const int tx = tid & 15, ty = tid >> 4;

    unsigned long long acc[4][2];
#pragma unroll
    for (int i = 0; i < 4; i++) { acc[i][0] = 0ull; acc[i][1] = 0ull; }

    const int lr = tid >> 2;
    const int lk = (tid & 3) << 2;
    const int wk = tid >> 4;
    const int wc = (tid & 15) << 2;

    for (int k0 = 0; k0 < H_; k0 += 16) {
        float4 gx = *(const float4*)&x[(row0 + lr) * H_ + k0 + lk];
        float4 gw = *(const float4*)&w[(k0 + wk) * K_ + col0 + wc];
        __syncthreads();
        sX[lk + 0][lr] = gx.x; sX[lk + 1][lr] = gx.y;
        sX[lk + 2][lr] = gx.z; sX[lk + 3][lr] = gx.w;
        *(float4*)&sW[wk][wc] = gw;
        __syncthreads();
#pragma unroll
        for (int kk = 0; kk < 16; kk++) {
            float4 a4 = *(const float4*)&sX[kk][ty * 4];
            float4 b4 = *(const float4*)&sW[kk][tx * 4];
            unsigned long long b01 = pack2(b4.x, b4.y);
            unsigned long long b23 = pack2(b4.z, b4.w);
            unsigned long long a0 = pack2(a4.x, a4.x);
            unsigned long long a1 = pack2(a4.y, a4.y);
            unsigned long long a2 = pack2(a4.z, a4.z);
            unsigned long long a3 = pack2(a4.w, a4.w);
            fma2(acc[0][0], a0, b01); fma2(acc[0][1], a0, b23);
            fma2(acc[1][0], a1, b01); fma2(acc[1][1], a1, b23);
            fma2(acc[2][0], a2, b01); fma2(acc[2][1], a2, b23);
            fma2(acc[3][0], a3, b01); fma2(acc[3][1], a3, b23);
        }
    }

    const int col = col0 + tx * 4;
#pragma unroll
    for (int i = 0; i < 4; i++) {
        float4 o;
        unpack2(acc[i][0], o.x, o.y);
        unpack2(acc[i][1], o.z, o.w);
        if (!z) {
            o.x += b_s[col + 0]; o.y += b_s[col + 1];
            o.z += b_s[col + 2]; o.w += b_s[col + 3];
        }
        *(float4*)&outp[(row0 + ty * 4 + i) * K_ + col] = o;
    }
}

// ---------------- Kernel 2: register-direct tanh -> mma.sync bf16-split, m32/warp ----
// CTA = 256 threads = 8 warps, ONE i-row x 256 j -> 2 CTAs/SM.
// Warp w: j-range = w*32 .. +32 (two m16 A-fragment sets).
// tanh = single MUFU.TANH (halves MUFU pressure vs ex2+rcp; frees fma/alu slots).
// Pass-major MMA: consecutive HMMAs hit 14 independent accumulators.
#define SVHI_OFF 1024
#define SVLO_OFF (SVHI_OFF + 56 * VSTRIDE * 4)
#define SMEM2_BYTES (SVHI_OFF + 2 * 56 * VSTRIDE * 4)   // 60160

__global__ __launch_bounds__(256) void fused_tanh_mma_kernel(
    const float* __restrict__ v, float* __restrict__ out)
{
    extern __shared__ char smem[];
    float*    sL   = (float*)smem;                  // 256 f32 (l row, bias folded)
    uint32_t* sVhi = (uint32_t*)(smem + SVHI_OFF);  // [56][VSTRIDE] b32 (k-pairs)
    uint32_t* sVlo = (uint32_t*)(smem + SVLO_OFF);

    const int tid = threadIdx.x;
    const int i = blockIdx.x;
    const int b = blockIdx.y;

    // stage l row
    sL[tid] = g_left[(size_t)(b * S_ + i) * K_ + tid];

    // stage V^T hi/lo: row n (0..55, zero-padded >=50), col kk packs (k=2kk, 2kk+1)
    for (int idx = tid; idx < 56 * 128; idx += 256) {
        int n = idx >> 7;
        int kk = idx & 127;
        int k = kk << 1;
        float v0 = 0.0f, v1 = 0.0f;
        if (n < P_) { v0 = v[k * P_ + n]; v1 = v[(k + 1) * P_ + n]; }
        uint32_t hp = bf16x2(v0, v1);
        uint32_t lp = bf16x2(v0 - lo16f(hp), v1 - hi16f(hp));
        sVhi[n * VSTRIDE + kk] = hp;
        sVlo[n * VSTRIDE + kk] = lp;
    }
    __syncthreads();

    const int w = tid >> 5, lane = tid & 31;
    const int group = lane >> 2, c = lane & 3;
    const int jb = w * 32;                  // warp's j base (32 rows)

    // 4 A rows per thread: j = jb+group, +8, +16, +24 (one base ptr + imm offsets)
    const float* rbase = g_right + (size_t)(b * S_ + jb + group) * K_ + 2 * c;

    float d0[7][4], d1[7][4];
#pragma unroll
    for (int nt = 0; nt < 7; nt++)
#pragma unroll
        for (int q = 0; q < 4; q++) { d0[nt][q] = 0.0f; d1[nt][q] = 0.0f; }

    // prefetch chunk 0 r-values (L2-resident; coalesced)
    float2 rlo[4], rhi[4];
#pragma unroll
    for (int s = 0; s < 4; s++) {
        rlo[s] = *(const float2*)(rbase + s * 8 * K_);
        rhi[s] = *(const float2*)(rbase + s * 8 * K_ + 8);
    }

#pragma unroll
    for (int ch = 0; ch < 16; ch++) {
        const int k0 = ch * 16;
        float2 l0 = *(const float2*)&sL[k0 + 2 * c];
        float2 l2 = *(const float2*)&sL[k0 + 2 * c + 8];

        // 16 tanh: FADD + MUFU.TANH each
        float tl[4][2], th[4][2];
#pragma unroll
        for (int s = 0; s < 4; s++) {
            tl[s][0] = tanh_fast(l0.x + rlo[s].x);
            tl[s][1] = tanh_fast(l0.y + rlo[s].y);
            th[s][0] = tanh_fast(l2.x + rhi[s].x);
            th[s][1] = tanh_fast(l2.y + rhi[s].y);
        }

        // prefetch next chunk's r while tanh/mma proceed
        if (ch < 15) {
#pragma unroll
            for (int s = 0; s < 4; s++) {
                rlo[s] = *(const float2*)(rbase + s * 8 * K_ + (ch + 1) * 16);
                rhi[s] = *(const float2*)(rbase + s * 8 * K_ + (ch + 1) * 16 + 8);
            }
        }

        // pack A fragments: set0 = rows (group, group+8), set1 = (group+16, +24)
        uint32_t aH[8], aL[8];
#pragma unroll
        for (int s = 0; s < 2; s++) {
            int ra = 2 * s, rb = 2 * s + 1;
            aH[4*s+0] = bf16x2(tl[ra][0], tl[ra][1]);
            aH[4*s+1] = bf16x2(tl[rb][0], tl[rb][1]);
            aH[4*s+2] = bf16x2(th[ra][0], th[ra][1]);
            aH[4*s+3] = bf16x2(th[rb][0], th[rb][1]);
            aL[4*s+0] = bf16x2(tl[ra][0] - lo16f(aH[4*s+0]), tl[ra][1] - hi16f(aH[4*s+0]));
            aL[4*s+1] = bf16x2(tl[rb][0] - lo16f(aH[4*s+1]), tl[rb][1] - hi16f(aH[4*s+1]));
            aL[4*s+2] = bf16x2(th[ra][0] - lo16f(aH[4*s+2]), th[ra][1] - hi16f(aH[4*s+2]));
            aL[4*s+3] = bf16x2(th[rb][0] - lo16f(aH[4*s+3]), th[rb][1] - hi16f(aH[4*s+3]));
        }

        const uint32_t* ph = sVhi + (ch << 3) + c;   // + n*VSTRIDE
        const uint32_t* pl = sVlo + (ch << 3) + c;

        // pass 1: hi*hi (14 independent HMMAs)
#pragma unroll
        for (int nt = 0; nt < 7; nt++) {
            const int off = (nt * 8 + group) * VSTRIDE;
            uint32_t b0 = ph[off], b1 = ph[off + 4];
            mma16816(d0[nt], aH[0], aH[1], aH[2], aH[3], b0, b1);
            mma16816(d1[nt], aH[4], aH[5], aH[6], aH[7], b0, b1);
        }
        // pass 2: lo*hi (B reloaded -- cheap LDS, keeps regs low)
#pragma unroll
        for (int nt = 0; nt < 7; nt++) {
            const int off = (nt * 8 + group) * VSTRIDE;
            uint32_t b0 = ph[off], b1 = ph[off + 4];
            mma16816(d0[nt], aL[0], aL[1], aL[2], aL[3], b0, b1);
            mma16816(d1[nt], aL[4], aL[5], aL[6], aL[7], b0, b1);
        }
        // pass 3: hi*lo
#pragma unroll
        for (int nt = 0; nt < 7; nt++) {
            const int off = (nt * 8 + group) * VSTRIDE;
            uint32_t b0 = pl[off], b1 = pl[off + 4];
            mma16816(d0[nt], aH[0], aH[1], aH[2], aH[3], b0, b1);
            mma16816(d1[nt], aH[4], aH[5], aH[6], aH[7], b0, b1);
        }
    }

    // epilogue: rows jb+group (+8, +16, +24), cols p = nt*8 + 2c (+1); only p<50
    float* obase = out + (size_t)(b * S_ + i) * S_ * P_ + (size_t)(jb + group) * P_;
#pragma unroll
    for (int nt = 0; nt < 7; nt++) {
        const int p0 = nt * 8 + 2 * c;
        if (p0 < P_) {   // p0 even, p0<=48 -> p0+1<=49 safe
            *(float2*)(obase + 0 * 8 * P_ + p0) = make_float2(d0[nt][0], d0[nt][1]);
            *(float2*)(obase + 1 * 8 * P_ + p0) = make_float2(d0[nt][2], d0[nt][3]);
            *(float2*)(obase + 2 * 8 * P_ + p0) = make_float2(d1[nt][0], d1[nt][1]);
            *(float2*)(obase + 3 * 8 * P_ + p0) = make_float2(d1[nt][2], d1[nt][3]);
        }
    }
}

extern "C" void kernel_launch(void* const* d_in, const int* in_sizes, int n_in,
                              void* d_out, int out_size) {
    const float* x   = (const float*)d_in[0];
    const float* u_a = (const float*)d_in[1];
    const float* w_a = (const float*)d_in[2];
    const float* b_s = (const float*)d_in[3];
    const float* v   = (const float*)d_in[4];
    float* out = (float*)d_out;

    cudaFuncSetAttribute(fused_tanh_mma_kernel,
                         cudaFuncAttributeMaxDynamicSharedMemorySize, SMEM2_BYTES);

    dim3 g1(K_ / 64, (B_ * S_) / 64, 2);      // (4, 32, 2)
    gemm_lr_kernel<<<g1, 256>>>(x, u_a, w_a, b_s);

    dim3 g2(S_, B_);                           // 2048 CTAs (1 i-row each, 2/SM)
    fused_tanh_mma_kernel<<<g2, 256, SMEM2_BYTES>>>(v, out);
}

// round 15
// speedup vs baseline: 1.0932x; 1.0001x over previous
#include <cuda_runtime.h>
#include <cuda_fp16.h>
#include <cstdint>

#define B_ 8
#define S_ 256
#define H_ 768
#define K_ 256
#define P_ 50
#define VSTRIDE 132    // V smem row stride in b32: bank = 4*group+c -> conflict-free

// Scratch for the two projection GEMMs (allocation-free rule: device globals)
__device__ __align__(16) float g_left [B_ * S_ * K_];   // left  = x@u_a + b_s
__device__ __align__(16) float g_right[B_ * S_ * K_];   // right = x@w_a

// ---------------- packed f32x2 helpers (Blackwell FFMA2 path) ----------------
__device__ __forceinline__ unsigned long long pack2(float a, float b) {
    unsigned long long r;
    asm("mov.b64 %0, {%1, %2};" : "=l"(r)
        : "r"(__float_as_uint(a)), "r"(__float_as_uint(b)));
    return r;
}
__device__ __forceinline__ void fma2(unsigned long long& d,
                                     unsigned long long a, unsigned long long b) {
    asm("fma.rn.f32x2 %0, %1, %2, %0;" : "+l"(d) : "l"(a), "l"(b));
}
__device__ __forceinline__ void unpack2(unsigned long long p, float& lo, float& hi) {
    unsigned int l, h;
    asm("mov.b64 {%0, %1}, %2;" : "=r"(l), "=r"(h) : "l"(p));
    lo = __uint_as_float(l);
    hi = __uint_as_float(h);
}

// ---------------- fp16 helpers ----------------
// pack two f32 -> f16x2; first arg lands in the LOW 16 bits
__device__ __forceinline__ uint32_t f16x2(float lo, float hi) {
    uint32_t r;
    asm("cvt.rn.f16x2.f32 %0, %1, %2;" : "=r"(r) : "f"(hi), "f"(lo));
    return r;
}

// HW tanh: single MUFU op (sm_75+, valid on base sm_100 target).
// Measured contribution to rel_err: ~2e-6 (R14).
__device__ __forceinline__ float tanh_fast(float a) {
    float r;
    asm("tanh.approx.f32 %0, %1;" : "=f"(r) : "f"(a));
    return r;
}

// classic warp-level fp16 MMA (sm_80+; works on sm_100 base target)
__device__ __forceinline__ void mma16816(float* d, uint32_t a0, uint32_t a1,
                                         uint32_t a2, uint32_t a3,
                                         uint32_t b0, uint32_t b1) {
    asm volatile(
        "mma.sync.aligned.m16n8k16.row.col.f32.f16.f16.f32 "
        "{%0,%1,%2,%3}, {%4,%5,%6,%7}, {%8,%9}, {%0,%1,%2,%3};"
        : "+f"(d[0]), "+f"(d[1]), "+f"(d[2]), "+f"(d[3])
        : "r"(a0), "r"(a1), "r"(a2), "r"(a3), "r"(b0), "r"(b1));
}

// ---------------- Kernel 1: left/right projections (fused bias) ----------------
__global__ __launch_bounds__(256) void gemm_lr_kernel(
    const float* __restrict__ x, const float* __restrict__ u_a,
    const float* __restrict__ w_a, const float* __restrict__ b_s)
{
    __shared__ float sX[16][64];
    __shared__ float sW[16][64];

    const int z = blockIdx.z;
    const float* __restrict__ w = z ? w_a : u_a;
    float* __restrict__ outp = z ? g_right : g_left;

    const int row0 = blockIdx.y * 64;
    const int col0 = blockIdx.x * 64;
    const int tid = threadIdx.x;
    const int tx = tid & 15, ty = tid >> 4;

    unsigned long long acc[4][2];
#pragma unroll
    for (int i = 0; i < 4; i++) { acc[i][0] = 0ull; acc[i][1] = 0ull; }

    const int lr = tid >> 2;
    const int lk = (tid & 3) << 2;
    const int wk = tid >> 4;
    const int wc = (tid & 15) << 2;

    for (int k0 = 0; k0 < H_; k0 += 16) {
        float4 gx = *(const float4*)&x[(row0 + lr) * H_ + k0 + lk];
        float4 gw = *(const float4*)&w[(k0 + wk) * K_ + col0 + wc];
        __syncthreads();
        sX[lk + 0][lr] = gx.x; sX[lk + 1][lr] = gx.y;
        sX[lk + 2][lr] = gx.z; sX[lk + 3][lr] = gx.w;
        *(float4*)&sW[wk][wc] = gw;
        __syncthreads();
#pragma unroll
        for (int kk = 0; kk < 16; kk++) {
            float4 a4 = *(const float4*)&sX[kk][ty * 4];
            float4 b4 = *(const float4*)&sW[kk][tx * 4];
            unsigned long long b01 = pack2(b4.x, b4.y);
            unsigned long long b23 = pack2(b4.z, b4.w);
            unsigned long long a0 = pack2(a4.x, a4.x);
            unsigned long long a1 = pack2(a4.y, a4.y);
            unsigned long long a2 = pack2(a4.z, a4.z);
            unsigned long long a3 = pack2(a4.w, a4.w);
            fma2(acc[0][0], a0, b01); fma2(acc[0][1], a0, b23);
            fma2(acc[1][0], a1, b01); fma2(acc[1][1], a1, b23);
            fma2(acc[2][0], a2, b01); fma2(acc[2][1], a2, b23);
            fma2(acc[3][0], a3, b01); fma2(acc[3][1], a3, b23);
        }
    }

    const int col = col0 + tx * 4;
#pragma unroll
    for (int i = 0; i < 4; i++) {
        float4 o;
        unpack2(acc[i][0], o.x, o.y);
        unpack2(acc[i][1], o.z, o.w);
        if (!z) {
            o.x += b_s[col + 0]; o.y += b_s[col + 1];
            o.z += b_s[col + 2]; o.w += b_s[col + 3];
        }
        *(float4*)&outp[(row0 + ty * 4 + i) * K_ + col] = o;
    }
}

// ---------------- Kernel 2: tanh -> mma.sync fp16, 2-pass V-split, m32/warp --------
// CTA = 256 threads = 8 warps, ONE i-row x 256 j -> 2 CTAs/SM.
// Warp w: j-range = w*32 .. +32 (two m16 A-fragment sets).
// t stored as SINGLE fp16 (rel err ~2^-12 -> ~1e-4 on output); V pre-split into
// fp16 hi + lo (exact reconstruction to subnormal dust). 2 accumulating passes:
// A*Vhi + A*Vlo -> 28 HMMA/chunk (was 42). Pass-major: 14 independent HMMAs.
#define SVHI_OFF 1024
#define SVLO_OFF (SVHI_OFF + 56 * VSTRIDE * 4)
#define SMEM2_BYTES (SVHI_OFF + 2 * 56 * VSTRIDE * 4)   // 60160

__global__ __launch_bounds__(256) void fused_tanh_mma_kernel(
    const float* __restrict__ v, float* __restrict__ out)
{
    extern __shared__ char smem[];
    float*    sL   = (float*)smem;                  // 256 f32 (l row, bias folded)
    uint32_t* sVhi = (uint32_t*)(smem + SVHI_OFF);  // [56][VSTRIDE] f16x2 (k-pairs)
    uint32_t* sVlo = (uint32_t*)(smem + SVLO_OFF);

    const int tid = threadIdx.x;
    const int i = blockIdx.x;
    const int b = blockIdx.y;

    // stage l row
    sL[tid] = g_left[(size_t)(b * S_ + i) * K_ + tid];

    // stage V^T fp16 hi/lo: row n (0..55, zero-padded >=50), col kk = (k, k+1) pair
    for (int idx = tid; idx < 56 * 128; idx += 256) {
        int n = idx >> 7;
        int kk = idx & 127;
        int k = kk << 1;
        float v0 = 0.0f, v1 = 0.0f;
        if (n < P_) { v0 = v[k * P_ + n]; v1 = v[(k + 1) * P_ + n]; }
        uint32_t hp = f16x2(v0, v1);
        __half2 h2 = *(__half2*)&hp;
        float2 back = __half22float2(h2);
        uint32_t lp = f16x2(v0 - back.x, v1 - back.y);
        sVhi[n * VSTRIDE + kk] = hp;
        sVlo[n * VSTRIDE + kk] = lp;
    }
    __syncthreads();

    const int w = tid >> 5, lane = tid & 31;
    const int group = lane >> 2, c = lane & 3;
    const int jb = w * 32;                  // warp's j base (32 rows)

    // 4 A rows per thread: j = jb+group, +8, +16, +24 (one base ptr + imm offsets)
    const float* rbase = g_right + (size_t)(b * S_ + jb + group) * K_ + 2 * c;

    float d0[7][4], d1[7][4];
#pragma unroll
    for (int nt = 0; nt < 7; nt++)
#pragma unroll
        for (int q = 0; q < 4; q++) { d0[nt][q] = 0.0f; d1[nt][q] = 0.0f; }

    // prefetch chunk 0 r-values (L2-resident; coalesced)
    float2 rlo[4], rhi[4];
#pragma unroll
    for (int s = 0; s < 4; s++) {
        rlo[s] = *(const float2*)(rbase + s * 8 * K_);
        rhi[s] = *(const float2*)(rbase + s * 8 * K_ + 8);
    }

#pragma unroll
    for (int ch = 0; ch < 16; ch++) {
        const int k0 = ch * 16;
        float2 l0 = *(const float2*)&sL[k0 + 2 * c];
        float2 l2 = *(const float2*)&sL[k0 + 2 * c + 8];

        // 16 tanh: FADD + MUFU.TANH each
        float tl[4][2], th[4][2];
#pragma unroll
        for (int s = 0; s < 4; s++) {
            tl[s][0] = tanh_fast(l0.x + rlo[s].x);
            tl[s][1] = tanh_fast(l0.y + rlo[s].y);
            th[s][0] = tanh_fast(l2.x + rhi[s].x);
            th[s][1] = tanh_fast(l2.y + rhi[s].y);
        }

        // prefetch next chunk's r while tanh/mma proceed
        if (ch < 15) {
#pragma unroll
            for (int s = 0; s < 4; s++) {
                rlo[s] = *(const float2*)(rbase + s * 8 * K_ + (ch + 1) * 16);
                rhi[s] = *(const float2*)(rbase + s * 8 * K_ + (ch + 1) * 16 + 8);
            }
        }

        // pack A fragments (single fp16): set0 = rows (group, +8), set1 = (+16, +24)
        uint32_t a[8];
#pragma unroll
        for (int s = 0; s < 2; s++) {
            int ra = 2 * s, rb = 2 * s + 1;
            a[4*s+0] = f16x2(tl[ra][0], tl[ra][1]);
            a[4*s+1] = f16x2(tl[rb][0], tl[rb][1]);
            a[4*s+2] = f16x2(th[ra][0], th[ra][1]);
            a[4*s+3] = f16x2(th[rb][0], th[rb][1]);
        }

        const uint32_t* ph = sVhi + (ch << 3) + c;   // + n*VSTRIDE
        const uint32_t* pl = sVlo + (ch << 3) + c;

        // pass 1: A * Vhi (14 independent HMMAs)
#pragma unroll
        for (int nt = 0; nt < 7; nt++) {
            const int off = (nt * 8 + group) * VSTRIDE;
            uint32_t b0 = ph[off], b1 = ph[off + 4];
            mma16816(d0[nt], a[0], a[1], a[2], a[3], b0, b1);
            mma16816(d1[nt], a[4], a[5], a[6], a[7], b0, b1);
        }
        // pass 2: A * Vlo
#pragma unroll
        for (int nt = 0; nt < 7; nt++) {
            const int off = (nt * 8 + group) * VSTRIDE;
            uint32_t b0 = pl[off], b1 = pl[off + 4];
            mma16816(d0[nt], a[0], a[1], a[2], a[3], b0, b1);
            mma16816(d1[nt], a[4], a[5], a[6], a[7], b0, b1);
        }
    }

    // epilogue: rows jb+group (+8, +16, +24), cols p = nt*8 + 2c (+1); only p<50
    float* obase = out + (size_t)(b * S_ + i) * S_ * P_ + (size_t)(jb + group) * P_;
#pragma unroll
    for (int nt = 0; nt < 7; nt++) {
        const int p0 = nt * 8 + 2 * c;
        if (p0 < P_) {   // p0 even, p0<=48 -> p0+1<=49 safe
            *(float2*)(obase + 0 * 8 * P_ + p0) = make_float2(d0[nt][0], d0[nt][1]);
            *(float2*)(obase + 1 * 8 * P_ + p0) = make_float2(d0[nt][2], d0[nt][3]);
            *(float2*)(obase + 2 * 8 * P_ + p0) = make_float2(d1[nt][0], d1[nt][1]);
            *(float2*)(obase + 3 * 8 * P_ + p0) = make_float2(d1[nt][2], d1[nt][3]);
        }
    }
}

extern "C" void kernel_launch(void* const* d_in, const int* in_sizes, int n_in,
                              void* d_out, int out_size) {
    const float* x   = (const float*)d_in[0];
    const float* u_a = (const float*)d_in[1];
    const float* w_a = (const float*)d_in[2];
    const float* b_s = (const float*)d_in[3];
    const float* v   = (const float*)d_in[4];
    float* out = (float*)d_out;

    cudaFuncSetAttribute(fused_tanh_mma_kernel,
                         cudaFuncAttributeMaxDynamicSharedMemorySize, SMEM2_BYTES);

    dim3 g1(K_ / 64, (B_ * S_) / 64, 2);      // (4, 32, 2)
    gemm_lr_kernel<<<g1, 256>>>(x, u_a, w_a, b_s);

    dim3 g2(S_, B_);                           // 2048 CTAs (1 i-row each, 2/SM)
    fused_tanh_mma_kernel<<<g2, 256, SMEM2_BYTES>>>(v, out);
}

// round 17
// speedup vs baseline: 1.2056x; 1.1028x over previous
#include <cuda_runtime.h>
#include <cuda_fp16.h>
#include <cstdint>

#define B_ 8
#define S_ 256
#define H_ 768
#define K_ 256
#define P_ 50
#define VSTRIDE 132    // V smem row stride in b32: bank = 4*group+c -> conflict-free

// Scratch for the two projection GEMMs (allocation-free rule: device globals)
__device__ __align__(16) float g_left [B_ * S_ * K_];   // left = x@u_a + b_s (row-major)
// right = x@w_a, CHUNK-TILED: [b][ch=k/16][j][k%16] -> fused-kernel gathers are
// 512B-contiguous per warp (4 L1 wavefronts/LDG.64 instead of 8 with row-major).
__device__ __align__(16) float g_right[B_ * S_ * K_];

// ---------------- packed f32x2 helpers (Blackwell FFMA2 path) ----------------
__device__ __forceinline__ unsigned long long pack2(float a, float b) {
    unsigned long long r;
    asm("mov.b64 %0, {%1, %2};" : "=l"(r)
        : "r"(__float_as_uint(a)), "r"(__float_as_uint(b)));
    return r;
}
__device__ __forceinline__ void fma2(unsigned long long& d,
                                     unsigned long long a, unsigned long long b) {
    asm("fma.rn.f32x2 %0, %1, %2, %0;" : "+l"(d) : "l"(a), "l"(b));
}
__device__ __forceinline__ void unpack2(unsigned long long p, float& lo, float& hi) {
    unsigned int l, h;
    asm("mov.b64 {%0, %1}, %2;" : "=r"(l), "=r"(h) : "l"(p));
    lo = __uint_as_float(l);
    hi = __uint_as_float(h);
}

// ---------------- fp16 helpers ----------------
// pack two f32 -> f16x2; first arg lands in the LOW 16 bits
__device__ __forceinline__ uint32_t f16x2(float lo, float hi) {
    uint32_t r;
    asm("cvt.rn.f16x2.f32 %0, %1, %2;" : "=r"(r) : "f"(hi), "f"(lo));
    return r;
}

// HW tanh: single MUFU op. Measured rel_err contribution ~2e-6 (R14).
__device__ __forceinline__ float tanh_fast(float a) {
    float r;
    asm("tanh.approx.f32 %0, %1;" : "=f"(r) : "f"(a));
    return r;
}

// classic warp-level fp16 MMA (sm_80+; works on sm_100 base target)
__device__ __forceinline__ void mma16816(float* d, uint32_t a0, uint32_t a1,
                                         uint32_t a2, uint32_t a3,
                                         uint32_t b0, uint32_t b1) {
    asm volatile(
        "mma.sync.aligned.m16n8k16.row.col.f32.f16.f16.f32 "
        "{%0,%1,%2,%3}, {%4,%5,%6,%7}, {%8,%9}, {%0,%1,%2,%3};"
        : "+f"(d[0]), "+f"(d[1]), "+f"(d[2]), "+f"(d[3])
        : "r"(a0), "r"(a1), "r"(a2), "r"(a3), "r"(b0), "r"(b1));
}

// ---------------- Kernel 1: left/right projections (fused bias) ----------------
// z==0: g_left (row-major, +bias). z==1: g_right (chunk-tiled [b][ch][j][16]).
__global__ __launch_bounds__(256) void gemm_lr_kernel(
    const float* __restrict__ x, const float* __restrict__ u_a,
    const float* __restrict__ w_a, const float* __restrict__ b_s)
{
    __shared__ float sX[16][64];
    __shared__ float sW[16][64];

    const int z = blockIdx.z;
    const float* __restrict__ w = z ? w_a : u_a;
    float* __restrict__ outp = z ? g_right : g_left;

    const int row0 = blockIdx.y * 64;
    const int col0 = blockIdx.x * 64;
    const int tid = threadIdx.x;
    const int tx = tid & 15, ty = tid >> 4;

    unsigned long long acc[4][2];
#pragma unroll
    for (int i = 0; i < 4; i++) { acc[i][0] = 0ull; acc[i][1] = 0ull; }

    const int lr = tid >> 2;
    const int lk = (tid & 3) << 2;
    const int wk = tid >> 4;
    const int wc = (tid & 15) << 2;

    for (int k0 = 0; k0 < H_; k0 += 16) {
        float4 gx = *(const float4*)&x[(row0 + lr) * H_ + k0 + lk];
        float4 gw = *(const float4*)&w[(k0 + wk) * K_ + col0 + wc];
        __syncthreads();
        sX[lk + 0][lr] = gx.x; sX[lk + 1][lr] = gx.y;
        sX[lk + 2][lr] = gx.z; sX[lk + 3][lr] = gx.w;
        *(float4*)&sW[wk][wc] = gw;
        __syncthreads();
#pragma unroll
        for (int kk = 0; kk < 16; kk++) {
            float4 a4 = *(const float4*)&sX[kk][ty * 4];
            float4 b4 = *(const float4*)&sW[kk][tx * 4];
            unsigned long long b01 = pack2(b4.x, b4.y);
            unsigned long long b23 = pack2(b4.z, b4.w);
            unsigned long long a0 = pack2(a4.x, a4.x);
            unsigned long long a1 = pack2(a4.y, a4.y);
            unsigned long long a2 = pack2(a4.z, a4.z);
            unsigned long long a3 = pack2(a4.w, a4.w);
            fma2(acc[0][0], a0, b01); fma2(acc[0][1], a0, b23);
            fma2(acc[1][0], a1, b01); fma2(acc[1][1], a1, b23);
            fma2(acc[2][0], a2, b01); fma2(acc[2][1], a2, b23);
            fma2(acc[3][0], a3, b01); fma2(acc[3][1], a3, b23);
        }
    }

    const int col = col0 + tx * 4;
#pragma unroll
    for (int i = 0; i < 4; i++) {
        float4 o;
        unpack2(acc[i][0], o.x, o.y);
        unpack2(acc[i][1], o.z, o.w);
        const int m = row0 + ty * 4 + i;
        if (!z) {
            o.x += b_s[col + 0]; o.y += b_s[col + 1];
            o.z += b_s[col + 2]; o.w += b_s[col + 3];
            *(float4*)&outp[m * K_ + col] = o;
        } else {
            // chunk-tiled: ((b*16 + k/16)*256 + j)*16 + k%16  (float4 stays intact)
            const int bb = m >> 8, j = m & 255;
            const int chh = col >> 4, klo = col & 15;
            *(float4*)&outp[((size_t)(bb * 16 + chh) * 256 + j) * 16 + klo] = o;
        }
    }
}

// ---------------- Kernel 2: tanh -> mma.sync fp16, 2-pass V-split, m32/warp --------
// CTA = 256 threads = 8 warps, ONE i-row x 256 j -> 3 CTAs/SM (launch_bounds cap ~84
// regs; R15 measured 83 so this squeezes in; 6 warps/SMSP hides LDG/LDS latency).
// r gathers hit the chunk-tiled g_right: 4 L1 wavefronts per LDG.64 (was 8).
#define SVHI_OFF 1024
#define SVLO_OFF (SVHI_OFF + 56 * VSTRIDE * 4)
#define SMEM2_BYTES (SVHI_OFF + 2 * 56 * VSTRIDE * 4)   // 60160

__global__ __launch_bounds__(256, 3) void fused_tanh_mma_kernel(
    const float* __restrict__ v, float* __restrict__ out)
{
    extern __shared__ char smem[];
    float*    sL   = (float*)smem;                  // 256 f32 (l row, bias folded)
    uint32_t* sVhi = (uint32_t*)(smem + SVHI_OFF);  // [56][VSTRIDE] f16x2 (k-pairs)
    uint32_t* sVlo = (uint32_t*)(smem + SVLO_OFF);

    const int tid = threadIdx.x;
    const int i = blockIdx.x;
    const int b = blockIdx.y;

    // stage l row
    sL[tid] = g_left[(size_t)(b * S_ + i) * K_ + tid];

    // stage V^T fp16 hi/lo: row n (0..55, zero-padded >=50), col kk = (k, k+1) pair
    for (int idx = tid; idx < 56 * 128; idx += 256) {
        int n = idx >> 7;
        int kk = idx & 127;
        int k = kk << 1;
        float v0 = 0.0f, v1 = 0.0f;
        if (n < P_) { v0 = v[k * P_ + n]; v1 = v[(k + 1) * P_ + n]; }
        uint32_t hp = f16x2(v0, v1);
        __half2 h2 = *(__half2*)&hp;
        float2 back = __half22float2(h2);
        uint32_t lp = f16x2(v0 - back.x, v1 - back.y);
        sVhi[n * VSTRIDE + kk] = hp;
        sVlo[n * VSTRIDE + kk] = lp;
    }
    __syncthreads();

    const int w = tid >> 5, lane = tid & 31;
    const int group = lane >> 2, c = lane & 3;
    const int jb = w * 32;                  // warp's j base (32 rows)

    // chunk-tiled r base for this thread: (b*16 + ch)*4096 + (jb+group+8s)*16 + 2c
    const float* rbase = g_right + (size_t)b * 16 * 4096 + (jb + group) * 16 + 2 * c;

    float d0[7][4], d1[7][4];
#pragma unroll
    for (int nt = 0; nt < 7; nt++)
#pragma unroll
        for (int q = 0; q < 4; q++) { d0[nt][q] = 0.0f; d1[nt][q] = 0.0f; }

    // prefetch chunk 0 r-values (contiguous 512B per warp per LDG)
    float2 rlo[4], rhi[4];
#pragma unroll
    for (int s = 0; s < 4; s++) {
        rlo[s] = *(const float2*)(rbase + s * 128);
        rhi[s] = *(const float2*)(rbase + s * 128 + 8);
    }

#pragma unroll
    for (int ch = 0; ch < 16; ch++) {
        const int k0 = ch * 16;
        float2 l0 = *(const float2*)&sL[k0 + 2 * c];
        float2 l2 = *(const float2*)&sL[k0 + 2 * c + 8];

        // 16 tanh: FADD + MUFU.TANH each
        float tl[4][2], th[4][2];
#pragma unroll
        for (int s = 0; s < 4; s++) {
            tl[s][0] = tanh_fast(l0.x + rlo[s].x);
            tl[s][1] = tanh_fast(l0.y + rlo[s].y);
            th[s][0] = tanh_fast(l2.x + rhi[s].x);
            th[s][1] = tanh_fast(l2.y + rhi[s].y);
        }

        // prefetch next chunk's r while tanh/mma proceed
        if (ch < 15) {
            const float* rnext = rbase + (size_t)(ch + 1) * 4096;
#pragma unroll
            for (int s = 0; s < 4; s++) {
                rlo[s] = *(const float2*)(rnext + s * 128);
                rhi[s] = *(const float2*)(rnext + s * 128 + 8);
            }
        }

        // pack A fragments (single fp16): set0 = rows (group, +8), set1 = (+16, +24)
        uint32_t a[8];
#pragma unroll
        for (int s = 0; s < 2; s++) {
            int ra = 2 * s, rb = 2 * s + 1;
            a[4*s+0] = f16x2(tl[ra][0], tl[ra][1]);
            a[4*s+1] = f16x2(tl[rb][0], tl[rb][1]);
            a[4*s+2] = f16x2(th[ra][0], th[ra][1]);
            a[4*s+3] = f16x2(th[rb][0], th[rb][1]);
        }

        const uint32_t* ph = sVhi + (ch << 3) + c;   // + n*VSTRIDE
        const uint32_t* pl = sVlo + (ch << 3) + c;

        // pass 1: A * Vhi (14 independent HMMAs)
#pragma unroll
        for (int nt = 0; nt < 7; nt++) {
            const int off = (nt * 8 + group) * VSTRIDE;
            uint32_t b0 = ph[off], b1 = ph[off + 4];
            mma16816(d0[nt], a[0], a[1], a[2], a[3], b0, b1);
            mma16816(d1[nt], a[4], a[5], a[6], a[7], b0, b1);
        }
        // pass 2: A * Vlo
#pragma unroll
        for (int nt = 0; nt < 7; nt++) {
            const int off = (nt * 8 + group) * VSTRIDE;
            uint32_t b0 = pl[off], b1 = pl[off + 4];
            mma16816(d0[nt], a[0], a[1], a[2], a[3], b0, b1);
            mma16816(d1[nt], a[4], a[5], a[6], a[7], b0, b1);
        }
    }

    // epilogue: rows jb+group (+8, +16, +24), cols p = nt*8 + 2c (+1); only p<50
    float* obase = out + (size_t)(b * S_ + i) * S_ * P_ + (size_t)(jb + group) * P_;
#pragma unroll
    for (int nt = 0; nt < 7; nt++) {
        const int p0 = nt * 8 + 2 * c;
        if (p0 < P_) {   // p0 even, p0<=48 -> p0+1<=49 safe
            *(float2*)(obase + 0 * 8 * P_ + p0) = make_float2(d0[nt][0], d0[nt][1]);
            *(float2*)(obase + 1 * 8 * P_ + p0) = make_float2(d0[nt][2], d0[nt][3]);
            *(float2*)(obase + 2 * 8 * P_ + p0) = make_float2(d1[nt][0], d1[nt][1]);
            *(float2*)(obase + 3 * 8 * P_ + p0) = make_float2(d1[nt][2], d1[nt][3]);
        }
    }
}

extern "C" void kernel_launch(void* const* d_in, const int* in_sizes, int n_in,
                              void* d_out, int out_size) {
    const float* x   = (const float*)d_in[0];
    const float* u_a = (const float*)d_in[1];
    const float* w_a = (const float*)d_in[2];
    const float* b_s = (const float*)d_in[3];
    const float* v   = (const float*)d_in[4];
    float* out = (float*)d_out;

    cudaFuncSetAttribute(fused_tanh_mma_kernel,
                         cudaFuncAttributeMaxDynamicSharedMemorySize, SMEM2_BYTES);

    dim3 g1(K_ / 64, (B_ * S_) / 64, 2);      // (4, 32, 2)
    gemm_lr_kernel<<<g1, 256>>>(x, u_a, w_a, b_s);

    dim3 g2(S_, B_);                           // 2048 CTAs (1 i-row each, 3/SM)
    fused_tanh_mma_kernel<<<g2, 256, SMEM2_BYTES>>>(v, out);
}